// round 8
// baseline (speedup 1.0000x reference)
#include <cuda_runtime.h>
#include <cuda_bf16.h>
#include <cstdint>

#define B_DIM 2
#define E_DIM 1024
#define C_DIM 128
#define R_REL 32

// Scratch: Gram matrices + pre-split bf16 copies of x.
__device__ float g_G[(size_t)B_DIM * E_DIM * E_DIM];
__device__ __nv_bfloat16 g_hi[(size_t)B_DIM * E_DIM * C_DIM];
__device__ __nv_bfloat16 g_lo[(size_t)B_DIM * E_DIM * C_DIM];

// ---------------------------------------------------------------------------
// Kernel 0: split x (fp32) into hi = bf16(x), lo = bf16(x - hi).
// 262144 elements; one float4 per thread.
// ---------------------------------------------------------------------------
__global__ __launch_bounds__(256) void split_kernel(const float* __restrict__ x) {
    const size_t i4 = (size_t)blockIdx.x * 256 + threadIdx.x;  // float4 index
    const float4 v = ((const float4*)x)[i4];

    __nv_bfloat162 h0 = __floats2bfloat162_rn(v.x, v.y);
    __nv_bfloat162 h1 = __floats2bfloat162_rn(v.z, v.w);
    float lx = v.x - __bfloat162float(__low2bfloat16(h0));
    float ly = v.y - __bfloat162float(__high2bfloat16(h0));
    float lz = v.z - __bfloat162float(__low2bfloat16(h1));
    float lw = v.w - __bfloat162float(__high2bfloat16(h1));
    __nv_bfloat162 l0 = __floats2bfloat162_rn(lx, ly);
    __nv_bfloat162 l1 = __floats2bfloat162_rn(lz, lw);

    ((__nv_bfloat162*)g_hi)[i4 * 2 + 0] = h0;
    ((__nv_bfloat162*)g_hi)[i4 * 2 + 1] = h1;
    ((__nv_bfloat162*)g_lo)[i4 * 2 + 0] = l0;
    ((__nv_bfloat162*)g_lo)[i4 * 2 + 1] = l1;
}

// ---------------------------------------------------------------------------
// Kernel 1: G[b] = X[b] @ X[b]^T via split-bf16 tensor-core GEMM.
// Three passes: hi@hi^T + lo@hi^T + hi@lo^T (drops lo@lo^T ~ 2^-18).
// Fill is now a pure bf16 copy from pre-split buffers (no conversion math).
// 64x64 tile per block, 128 threads, ldmatrix.x4 + mma.m16n8k16.bf16.
// ---------------------------------------------------------------------------
#define GSTRIDE 136   // bf16 per smem row (128 + 8 pad): 272B, 16B-aligned rows

__device__ __forceinline__ uint32_t ldsm_addr(const __nv_bfloat16* p) {
    return (uint32_t)__cvta_generic_to_shared(p);
}

__global__ __launch_bounds__(128) void gram_mma_kernel() {
    const int b    = blockIdx.z;
    const size_t xoff = (size_t)b * E_DIM * C_DIM;
    float* Gb      = g_G + (size_t)b * E_DIM * E_DIM;

    const int row0 = blockIdx.y * 64;
    const int col0 = blockIdx.x * 64;
    const int tid  = threadIdx.x;
    const int lane = tid & 31;
    const int wid  = tid >> 5;
    const int wm   = wid >> 1;       // warp row (0..1) -> 32 rows
    const int wn   = wid & 1;        // warp col (0..1) -> 32 cols

    __shared__ __align__(16) __nv_bfloat16 As[64][GSTRIDE];
    __shared__ __align__(16) __nv_bfloat16 Bs[64][GSTRIDE];

    float acc[2][4][4];
    #pragma unroll
    for (int i = 0; i < 2; i++)
        #pragma unroll
        for (int j = 0; j < 4; j++)
            #pragma unroll
            for (int k = 0; k < 4; k++) acc[i][j][k] = 0.f;

    // Fill indexing: thread handles row rr, one 64-col half (128B = 8 uint4).
    const int rr    = tid >> 1;         // 0..63
    const int halfc = (tid & 1) * 64;   // bf16 column offset

    // Pass sources: A <- {hi, lo, hi}, B <- {hi, hi, lo}.
    const __nv_bfloat16* srcsA[3] = {g_hi, g_lo, g_hi};
    const __nv_bfloat16* srcsB[3] = {g_hi, g_hi, g_lo};

    #pragma unroll
    for (int chunk = 0; chunk < 3; chunk++) {
        const uint4* srcA = (const uint4*)(srcsA[chunk] + xoff +
                              (size_t)(row0 + rr) * C_DIM + halfc);
        const uint4* srcB = (const uint4*)(srcsB[chunk] + xoff +
                              (size_t)(col0 + rr) * C_DIM + halfc);
        uint4* dstA = (uint4*)&As[rr][halfc];
        uint4* dstB = (uint4*)&Bs[rr][halfc];
        #pragma unroll
        for (int i = 0; i < 8; i++) {
            dstA[i] = srcA[i];
            dstB[i] = srcB[i];
        }
        __syncthreads();

        // ---- 8 k16-steps over this chunk ----
        #pragma unroll
        for (int ks = 0; ks < 8; ks++) {
            uint32_t a[2][4];
            #pragma unroll
            for (int mt = 0; mt < 2; mt++) {
                int r = wm * 32 + mt * 16 + ((lane >> 3) & 1) * 8 + (lane & 7);
                int c = ks * 16 + (lane >> 4) * 8;
                uint32_t addr = ldsm_addr(&As[r][c]);
                asm volatile("ldmatrix.sync.aligned.m8n8.x4.shared.b16 {%0,%1,%2,%3}, [%4];"
                             : "=r"(a[mt][0]), "=r"(a[mt][1]), "=r"(a[mt][2]), "=r"(a[mt][3])
                             : "r"(addr));
            }
            uint32_t bf[2][4];
            #pragma unroll
            for (int p = 0; p < 2; p++) {
                int r = wn * 32 + p * 16 + ((lane >> 4) & 1) * 8 + (lane & 7);
                int c = ks * 16 + ((lane >> 3) & 1) * 8;
                uint32_t addr = ldsm_addr(&Bs[r][c]);
                asm volatile("ldmatrix.sync.aligned.m8n8.x4.shared.b16 {%0,%1,%2,%3}, [%4];"
                             : "=r"(bf[p][0]), "=r"(bf[p][1]), "=r"(bf[p][2]), "=r"(bf[p][3])
                             : "r"(addr));
            }
            #pragma unroll
            for (int mt = 0; mt < 2; mt++) {
                #pragma unroll
                for (int nt = 0; nt < 4; nt++) {
                    uint32_t b0 = bf[nt >> 1][(nt & 1) * 2 + 0];
                    uint32_t b1 = bf[nt >> 1][(nt & 1) * 2 + 1];
                    asm volatile(
                        "mma.sync.aligned.m16n8k16.row.col.f32.bf16.bf16.f32 "
                        "{%0,%1,%2,%3}, {%4,%5,%6,%7}, {%8,%9}, {%0,%1,%2,%3};"
                        : "+f"(acc[mt][nt][0]), "+f"(acc[mt][nt][1]),
                          "+f"(acc[mt][nt][2]), "+f"(acc[mt][nt][3])
                        : "r"(a[mt][0]), "r"(a[mt][1]), "r"(a[mt][2]), "r"(a[mt][3]),
                          "r"(b0), "r"(b1));
                }
            }
        }
        __syncthreads();
    }

    // ---- epilogue: write G tile ----
    #pragma unroll
    for (int mt = 0; mt < 2; mt++) {
        #pragma unroll
        for (int nt = 0; nt < 4; nt++) {
            int r = row0 + wm * 32 + mt * 16 + (lane >> 2);
            int c = col0 + wn * 32 + nt * 8 + (lane & 3) * 2;
            float2 v0 = make_float2(acc[mt][nt][0], acc[mt][nt][1]);
            float2 v1 = make_float2(acc[mt][nt][2], acc[mt][nt][3]);
            *(float2*)&Gb[(size_t)r * E_DIM + c]       = v0;
            *(float2*)&Gb[(size_t)(r + 8) * E_DIM + c] = v1;
        }
    }
}

// ---------------------------------------------------------------------------
// Kernel 2 (best measured config): out[b,s,r,o] = G[b,s,o] * R[r,s,o]
// One block per (s, 8-r chunk). All 8 R rows preloaded (explicit MLP=8),
// G rows in registers (L2-resident reads), outputs streamed with __stcs.
// ---------------------------------------------------------------------------
#define RCHUNK 8

__global__ __launch_bounds__(256) void scale_kernel(const float4* __restrict__ Rrel,
                                                    float4* __restrict__ out) {
    const int E4  = E_DIM / 4;                 // 256 float4 per row
    const int bid = blockIdx.x;
    const int s   = bid >> 2;                  // / (R_REL/RCHUNK)
    const int rc  = (bid & 3) * RCHUNK;
    const int t   = threadIdx.x;               // 0..255

    const float4* G = (const float4*)g_G;
    float4 g0 = __ldg(&G[(size_t)s * E4 + t]);
    float4 g1 = __ldg(&G[((size_t)E_DIM + s) * E4 + t]);

    float4 rv[RCHUNK];
    #pragma unroll
    for (int rr = 0; rr < RCHUNK; rr++)
        rv[rr] = __ldcs(&Rrel[((size_t)(rc + rr) * E_DIM + s) * E4 + t]);

    #pragma unroll
    for (int rr = 0; rr < RCHUNK; rr++) {
        const int r = rc + rr;
        float4 o0, o1;
        o0.x = g0.x * rv[rr].x;  o0.y = g0.y * rv[rr].y;
        o0.z = g0.z * rv[rr].z;  o0.w = g0.w * rv[rr].w;
        o1.x = g1.x * rv[rr].x;  o1.y = g1.y * rv[rr].y;
        o1.z = g1.z * rv[rr].z;  o1.w = g1.w * rv[rr].w;

        size_t base0 = (((size_t)s) * R_REL + r) * (size_t)E4 + t;
        size_t base1 = (((size_t)E_DIM + s) * R_REL + r) * (size_t)E4 + t;
        __stcs(&out[base0], o0);
        __stcs(&out[base1], o1);
    }
}

extern "C" void kernel_launch(void* const* d_in, const int* in_sizes, int n_in,
                              void* d_out, int out_size) {
    const float* x  = (const float*)d_in[0];   // (B, E, C) fp32
    const float* Rr = (const float*)d_in[1];   // (R_REL, E, E) fp32
    float* out      = (float*)d_out;           // (B, E, R_REL, E) fp32

    // 262144 floats = 65536 float4 -> 256 blocks x 256 threads.
    split_kernel<<<(B_DIM * E_DIM * C_DIM / 4) / 256, 256>>>(x);

    dim3 ggrid(E_DIM / 64, E_DIM / 64, B_DIM); // 16 x 16 x 2 = 512 blocks
    gram_mma_kernel<<<ggrid, 128>>>();

    scale_kernel<<<E_DIM * (R_REL / RCHUNK), 256>>>((const float4*)Rr, (float4*)out);

    (void)in_sizes; (void)n_in; (void)out_size;
}

// round 9
// speedup vs baseline: 1.2251x; 1.2251x over previous
#include <cuda_runtime.h>
#include <cuda_bf16.h>
#include <cstdint>

#define B_DIM 2
#define E_DIM 1024
#define C_DIM 128
#define R_REL 32

#define MT 32          // s rows per block
#define NT 32          // o cols per block
#define GSTRIDE 136    // bf16 per smem operand row (128 + 8): 272B, LDSM-safe
#define GS 36          // floats per smem G row (32 + 4): 144B, float4-safe

// Dynamic smem layout (bytes):
//   sA: [2][2][MT][GSTRIDE] bf16   A tiles (batch, hi/lo)      34816
//   sB: [2][2][NT][GSTRIDE] bf16   B tiles (batch, hi/lo)      34816
//   sG: [2][MT][GS] float          G tiles                      9216
#define SA_OFF 0
#define SB_OFF 34816
#define SG_OFF 69632
#define SMEM_BYTES 78848

__device__ __forceinline__ uint32_t ldsm_addr(const __nv_bfloat16* p) {
    return (uint32_t)__cvta_generic_to_shared(p);
}

__global__ __launch_bounds__(256, 2) void fused_kernel(const float* __restrict__ x,
                                                       const float4* __restrict__ Rrel,
                                                       float4* __restrict__ out) {
    extern __shared__ char smem[];
    __nv_bfloat16* sA = (__nv_bfloat16*)(smem + SA_OFF);
    __nv_bfloat16* sB = (__nv_bfloat16*)(smem + SB_OFF);
    float*         sG = (float*)(smem + SG_OFF);

    const int o0 = blockIdx.x * NT;
    const int s0 = blockIdx.y * MT;
    const int tid  = threadIdx.x;
    const int lane = tid & 31;
    const int wid  = tid >> 5;

    // ---------------- Phase 1: load x rows, split hi/lo into smem ----------
    // Thread t: row = t>>3 (0..31), col4 = t&7; 4 float4 per (region,batch).
    {
        const int row  = tid >> 3;
        const int col4 = tid & 7;
        #pragma unroll
        for (int reg = 0; reg < 2; reg++) {          // 0 = A (s rows), 1 = B (o rows)
            const int grow = (reg ? o0 : s0) + row;
            __nv_bfloat16* dst = reg ? sB : sA;
            #pragma unroll
            for (int b = 0; b < 2; b++) {
                const float4* src = (const float4*)(x + ((size_t)b * E_DIM + grow) * C_DIM);
                __nv_bfloat16* dhi = dst + ((b * 2 + 0) * MT + row) * GSTRIDE;
                __nv_bfloat16* dlo = dst + ((b * 2 + 1) * MT + row) * GSTRIDE;
                #pragma unroll
                for (int i = 0; i < 4; i++) {
                    const int c4 = col4 + i * 8;      // 0..31 float4 cols
                    float4 v = src[c4];
                    __nv_bfloat162 h0 = __floats2bfloat162_rn(v.x, v.y);
                    __nv_bfloat162 h1 = __floats2bfloat162_rn(v.z, v.w);
                    float lx = v.x - __bfloat162float(__low2bfloat16(h0));
                    float ly = v.y - __bfloat162float(__high2bfloat16(h0));
                    float lz = v.z - __bfloat162float(__low2bfloat16(h1));
                    float lw = v.w - __bfloat162float(__high2bfloat16(h1));
                    ((__nv_bfloat162*)(dhi + c4 * 4))[0] = h0;
                    ((__nv_bfloat162*)(dhi + c4 * 4))[1] = h1;
                    ((__nv_bfloat162*)(dlo + c4 * 4))[0] = __floats2bfloat162_rn(lx, ly);
                    ((__nv_bfloat162*)(dlo + c4 * 4))[1] = __floats2bfloat162_rn(lz, lw);
                }
            }
        }
    }
    __syncthreads();

    // ---------------- Phase 2: split-bf16 MMA (validated geometry) ---------
    // 8 warps: b = wid>>2, wm = (wid>>1)&1, wn = wid&1; warp tile 16m x 16n.
    {
        const int wb = wid >> 2;
        const int wm = (wid >> 1) & 1;
        const int wn = wid & 1;

        float acc[2][4];
        #pragma unroll
        for (int j = 0; j < 2; j++)
            #pragma unroll
            for (int k = 0; k < 4; k++) acc[j][k] = 0.f;

        const int paT[3] = {0, 1, 0};   // A part per pass: hi, lo, hi
        const int pbT[3] = {0, 0, 1};   // B part per pass: hi, hi, lo

        #pragma unroll
        for (int pass = 0; pass < 3; pass++) {
            const __nv_bfloat16* Ab = sA + ((wb * 2 + paT[pass]) * MT) * GSTRIDE;
            const __nv_bfloat16* Bb = sB + ((wb * 2 + pbT[pass]) * NT) * GSTRIDE;
            #pragma unroll
            for (int ks = 0; ks < 8; ks++) {
                uint32_t a[4];
                {
                    int r = wm * 16 + ((lane >> 3) & 1) * 8 + (lane & 7);
                    int c = ks * 16 + (lane >> 4) * 8;
                    uint32_t addr = ldsm_addr(Ab + r * GSTRIDE + c);
                    asm volatile("ldmatrix.sync.aligned.m8n8.x4.shared.b16 {%0,%1,%2,%3}, [%4];"
                                 : "=r"(a[0]), "=r"(a[1]), "=r"(a[2]), "=r"(a[3])
                                 : "r"(addr));
                }
                uint32_t bf[4];
                {
                    int r = wn * 16 + ((lane >> 4) & 1) * 8 + (lane & 7);
                    int c = ks * 16 + ((lane >> 3) & 1) * 8;
                    uint32_t addr = ldsm_addr(Bb + r * GSTRIDE + c);
                    asm volatile("ldmatrix.sync.aligned.m8n8.x4.shared.b16 {%0,%1,%2,%3}, [%4];"
                                 : "=r"(bf[0]), "=r"(bf[1]), "=r"(bf[2]), "=r"(bf[3])
                                 : "r"(addr));
                }
                #pragma unroll
                for (int nt = 0; nt < 2; nt++) {
                    asm volatile(
                        "mma.sync.aligned.m16n8k16.row.col.f32.bf16.bf16.f32 "
                        "{%0,%1,%2,%3}, {%4,%5,%6,%7}, {%8,%9}, {%0,%1,%2,%3};"
                        : "+f"(acc[nt][0]), "+f"(acc[nt][1]),
                          "+f"(acc[nt][2]), "+f"(acc[nt][3])
                        : "r"(a[0]), "r"(a[1]), "r"(a[2]), "r"(a[3]),
                          "r"(bf[nt * 2 + 0]), "r"(bf[nt * 2 + 1]));
                }
            }
        }

        // Write G warp tile to smem.
        #pragma unroll
        for (int nt = 0; nt < 2; nt++) {
            int m = wm * 16 + (lane >> 2);
            int n = wn * 16 + nt * 8 + (lane & 3) * 2;
            float* g = sG + (wb * MT + m) * GS + n;
            *(float2*)g            = make_float2(acc[nt][0], acc[nt][1]);
            *(float2*)(g + 8 * GS) = make_float2(acc[nt][2], acc[nt][3]);
        }
    }
    __syncthreads();

    // ---------------- Phase 3: streaming epilogue --------------------------
    // Thread t: o4 = t&7 (8 float4 across NT), si = t>>3 (0..31 s rows).
    {
        const int o4 = tid & 7;
        const int si = tid >> 3;
        const int E4 = E_DIM / 4;                     // 256
        const int sg = s0 + si;
        const int o4g = (o0 >> 2) + o4;

        const float4 g0 = *(const float4*)(sG + (0 * MT + si) * GS + o4 * 4);
        const float4 g1 = *(const float4*)(sG + (1 * MT + si) * GS + o4 * 4);

        const size_t rstep = (size_t)E_DIM * E4;      // R float4 stride per r
        const size_t rbase = (size_t)sg * E4 + o4g;
        const size_t ob0   = ((size_t)sg * R_REL) * E4 + o4g;
        const size_t ob1   = (((size_t)E_DIM + sg) * R_REL) * E4 + o4g;

        #pragma unroll
        for (int rc = 0; rc < R_REL; rc += 8) {
            float4 rv[8];
            #pragma unroll
            for (int rr = 0; rr < 8; rr++)
                rv[rr] = __ldcs(&Rrel[(size_t)(rc + rr) * rstep + rbase]);

            #pragma unroll
            for (int rr = 0; rr < 8; rr++) {
                const int r = rc + rr;
                float4 a, c;
                a.x = g0.x * rv[rr].x;  a.y = g0.y * rv[rr].y;
                a.z = g0.z * rv[rr].z;  a.w = g0.w * rv[rr].w;
                c.x = g1.x * rv[rr].x;  c.y = g1.y * rv[rr].y;
                c.z = g1.z * rv[rr].z;  c.w = g1.w * rv[rr].w;
                __stcs(&out[ob0 + (size_t)r * E4], a);
                __stcs(&out[ob1 + (size_t)r * E4], c);
            }
        }
    }
}

extern "C" void kernel_launch(void* const* d_in, const int* in_sizes, int n_in,
                              void* d_out, int out_size) {
    const float* x  = (const float*)d_in[0];   // (B, E, C) fp32
    const float* Rr = (const float*)d_in[1];   // (R_REL, E, E) fp32
    float* out      = (float*)d_out;           // (B, E, R_REL, E) fp32

    cudaFuncSetAttribute(fused_kernel,
                         cudaFuncAttributeMaxDynamicSharedMemorySize, SMEM_BYTES);

    dim3 grid(E_DIM / NT, E_DIM / MT);         // 32 x 32 = 1024 blocks
    fused_kernel<<<grid, 256, SMEM_BYTES>>>(x, (const float4*)Rr, (float4*)out);

    (void)in_sizes; (void)n_in; (void)out_size;
}